// round 1
// baseline (speedup 1.0000x reference)
#include <cuda_runtime.h>
#include <cuda_bf16.h>

// ---------------- scratch buffers (static device globals; no allocation) ----
__device__ float g_buf1[64u*32u*132u*132u]; // conv1 out               (142.7 MB)
__device__ float g_buf2[64u*32u*66u*66u];   // region+pool+bn2 out     (35.7 MB)
__device__ float g_buf3[64u*16u*59u*59u];   // conv2 out
__device__ float g_buf4[64u*16u*52u*52u];   // conv3 out
__device__ float g_buf5[64u*16u*24u*24u];   // conv4 out
__device__ float g_buf6[64u*16u*20u*20u];   // conv5 out (= fc input, 6400/b)
__device__ float g_fc1o[64u*4096u];
__device__ float g_fc2o[64u*2048u];

// ===========================================================================
// conv1: (64,3,142,142) -> (64,32,132,132), 11x11 VALID
// block 16x16 threads, each thread 2x2 px for 8 out channels; 32x32 out tile
// ===========================================================================
__global__ void conv1_kernel(const float* __restrict__ x,
                             const float* __restrict__ w,
                             const float* __restrict__ bias,
                             float* __restrict__ out) {
    __shared__ float s_in[3][42][42];
    __shared__ float s_w[8*3*11*11]; // 2904
    const int tile = blockIdx.x;
    const int tx0 = (tile % 5) * 32, ty0 = (tile / 5) * 32;
    const int ocg = blockIdx.y;
    const int b = blockIdx.z;
    const int tid = threadIdx.y * 16 + threadIdx.x;

    for (int i = tid; i < 8*363; i += 256)
        s_w[i] = w[ocg*8*363 + i];
    for (int i = tid; i < 3*42*42; i += 256) {
        int c = i / (42*42);
        int rr = (i / 42) % 42, cc = i % 42;
        int iy = ty0 + rr, ix = tx0 + cc;
        float v = 0.f;
        if (iy < 142 && ix < 142)
            v = x[((b*3 + c)*142 + iy)*142 + ix];
        s_in[c][rr][cc] = v;
    }
    __syncthreads();

    const int px = threadIdx.x * 2, py = threadIdx.y * 2;
    float acc[8][2][2];
#pragma unroll
    for (int o = 0; o < 8; o++)
#pragma unroll
        for (int dy = 0; dy < 2; dy++)
#pragma unroll
            for (int dx = 0; dx < 2; dx++) acc[o][dy][dx] = 0.f;

    for (int c = 0; c < 3; c++) {
        for (int ky = 0; ky < 11; ky++) {
            float in0[12], in1[12];
#pragma unroll
            for (int j = 0; j < 12; j++) {
                in0[j] = s_in[c][py + ky][px + j];
                in1[j] = s_in[c][py + ky + 1][px + j];
            }
#pragma unroll
            for (int kx = 0; kx < 11; kx++) {
#pragma unroll
                for (int o = 0; o < 8; o++) {
                    float wv = s_w[(o*3 + c)*121 + ky*11 + kx];
                    acc[o][0][0] += in0[kx]     * wv;
                    acc[o][0][1] += in0[kx + 1] * wv;
                    acc[o][1][0] += in1[kx]     * wv;
                    acc[o][1][1] += in1[kx + 1] * wv;
                }
            }
        }
    }
#pragma unroll
    for (int o = 0; o < 8; o++) {
        float bs = bias[ocg*8 + o];
#pragma unroll
        for (int dy = 0; dy < 2; dy++) {
            int oy = ty0 + py + dy;
            if (oy >= 132) continue;
#pragma unroll
            for (int dx = 0; dx < 2; dx++) {
                int ox = tx0 + px + dx;
                if (ox >= 132) continue;
                out[(((long)b*32 + ocg*8 + o)*132 + oy)*132 + ox] = acc[o][dy][dx] + bs;
            }
        }
    }
}

// ===========================================================================
// region layer fused: per-tile BN+ReLU -> 3x3 'same' conv -> +cb +residual
// -> ReLU -> maxpool2x2 -> BN2.  One block per (tile, batch). 288 threads.
// ===========================================================================
__global__ void region_kernel(const float* __restrict__ xin,
                              const float* __restrict__ rg_g, const float* __restrict__ rg_b,
                              const float* __restrict__ rg_m, const float* __restrict__ rg_v,
                              const float* __restrict__ rg_w, const float* __restrict__ rg_cb,
                              const float* __restrict__ bn2_g, const float* __restrict__ bn2_b,
                              const float* __restrict__ bn2_m, const float* __restrict__ bn2_v,
                              float* __restrict__ out) {
    __shared__ float smem[11008];           // s_in (<=6400) | s_w (4608); reused for staging
    __shared__ float s_scale[32], s_shift[32], s_cb[32], s_a2[32], s_b2[32];

    const int tile = blockIdx.x;
    const int b = blockIdx.y;
    const int ti = tile >> 3, tj = tile & 7;
    const int th = (ti < 7) ? 18 : 6, tw = (tj < 7) ? 18 : 6;
    const int gy0 = ti * 18, gx0 = tj * 18;
    const int tid = threadIdx.x;

    if (tid < 32) {
        int p = tile*32 + tid;
        float a = rg_g[p] * rsqrtf(rg_v[p] + 1e-5f);
        s_scale[tid] = a;
        s_shift[tid] = rg_b[p] - rg_m[p]*a;
        s_cb[tid]    = rg_cb[p];
    } else if (tid < 64) {
        int c = tid - 32;
        float a2 = bn2_g[c] * rsqrtf(bn2_v[c] + 1e-5f);
        s_a2[c] = a2;
        s_b2[c] = bn2_b[c] - bn2_m[c]*a2;
    }

    const int hp = th + 2, wp = tw + 2;
    const int wstrips = tw / 6;
    const int n_tasks = 32 * th * wstrips;
    float* s_in = smem;
    float* s_w  = smem + 6400;

    float acc[6][6];
#pragma unroll
    for (int s = 0; s < 6; s++)
#pragma unroll
        for (int j = 0; j < 6; j++) acc[s][j] = 0.f;

    for (int chunk = 0; chunk < 2; chunk++) {
        const int ic0 = chunk * 16;
        __syncthreads();
        const int nin = 16 * hp * wp;
        for (int i = tid; i < nin; i += 288) {
            int icl = i / (hp*wp);
            int r = i % (hp*wp);
            int y = r / wp, xx = r % wp;
            float v = 0.f;
            if (y > 0 && y < hp-1 && xx > 0 && xx < wp-1) {
                float raw = xin[(((long)b*32 + ic0 + icl)*132 + gy0 + y - 1)*132 + gx0 + xx - 1];
                v = fmaxf(s_scale[ic0+icl]*raw + s_shift[ic0+icl], 0.f);
            }
            s_in[i] = v;
        }
        for (int i = tid; i < 32*16*9; i += 288) {
            int oc = i / 144;
            int r = i % 144;
            s_w[i] = rg_w[(long)tile*9216 + oc*288 + ic0*9 + r];
        }
        __syncthreads();

#pragma unroll
        for (int s = 0; s < 6; s++) {
            int task = tid + s*288;
            if (task < n_tasks) {
                int oc  = task / (th*wstrips);
                int r   = task % (th*wstrips);
                int row = r / wstrips;
                int col = (r % wstrips) * 6;
                const float* wb = &s_w[oc*144];
                for (int icl = 0; icl < 16; icl++) {
                    const float* ib = &s_in[icl*hp*wp + row*wp + col];
#pragma unroll
                    for (int ky = 0; ky < 3; ky++) {
                        float iv[8];
#pragma unroll
                        for (int j = 0; j < 8; j++) iv[j] = ib[ky*wp + j];
#pragma unroll
                        for (int kx = 0; kx < 3; kx++) {
                            float wv = wb[icl*9 + ky*3 + kx];
#pragma unroll
                            for (int j = 0; j < 6; j++) acc[s][j] += iv[kx + j] * wv;
                        }
                    }
                }
            }
        }
    }

    __syncthreads();
    // stage: conv + cb + residual, ReLU
#pragma unroll
    for (int s = 0; s < 6; s++) {
        int task = tid + s*288;
        if (task < n_tasks) {
            int oc  = task / (th*wstrips);
            int r   = task % (th*wstrips);
            int row = r / wstrips;
            int col = (r % wstrips) * 6;
#pragma unroll
            for (int j = 0; j < 6; j++) {
                float res = xin[(((long)b*32 + oc)*132 + gy0 + row)*132 + gx0 + col + j];
                smem[(oc*th + row)*tw + col + j] = fmaxf(acc[s][j] + s_cb[oc] + res, 0.f);
            }
        }
    }
    __syncthreads();

    // maxpool 2x2 + bn2
    const int ph = th / 2, pw = tw / 2;
    const int npool = 32 * ph * pw;
    for (int i = tid; i < npool; i += 288) {
        int c = i / (ph*pw);
        int r = i % (ph*pw);
        int py = r / pw, px = r % pw;
        const float* base = &smem[(c*th + 2*py)*tw + 2*px];
        float m0 = fmaxf(base[0], base[1]);
        float m1 = fmaxf(base[tw], base[tw+1]);
        float m = fmaxf(m0, m1);
        out[(((long)b*32 + c)*66 + ti*9 + py)*66 + tj*9 + px] = s_a2[c]*m + s_b2[c];
    }
}

// ===========================================================================
// conv2 / conv3: 8x8 VALID, OC=16, +ReLU. Block: 8x16 output tile, 256 thr.
// Each thread: one 1x8 strip for one oc. IC chunked by 8.
// ===========================================================================
template<int CIN, int HIN, int WIN, int HOUT, int WOUT>
__global__ void conv8x8_relu_kernel(const float* __restrict__ in,
                                    const float* __restrict__ w,
                                    const float* __restrict__ bias,
                                    float* __restrict__ out) {
    __shared__ float s_in[8][15][23];
    __shared__ float s_w[16*8*64]; // 8192
    const int x0 = blockIdx.x * 16, y0 = blockIdx.y * 8;
    const int b = blockIdx.z;
    const int tid = threadIdx.x;
    const int oc = tid >> 4;
    const int rr = tid & 15;
    const int row = rr >> 1;
    const int cs = (rr & 1) * 8;

    float acc[8];
#pragma unroll
    for (int j = 0; j < 8; j++) acc[j] = 0.f;

    for (int chunk = 0; chunk < CIN/8; chunk++) {
        const int ic0 = chunk * 8;
        __syncthreads();
        for (int i = tid; i < 8*15*23; i += 256) {
            int icl = i / (15*23);
            int r = (i / 23) % 15, c = i % 23;
            int iy = y0 + r, ix = x0 + c;
            float v = 0.f;
            if (iy < HIN && ix < WIN)
                v = in[(((long)b*CIN + ic0 + icl)*HIN + iy)*WIN + ix];
            s_in[icl][r][c] = v;
        }
        for (int i = tid; i < 16*8*64; i += 256) {
            int o = i >> 9;
            int r = i & 511;
            s_w[i] = w[o*CIN*64 + ic0*64 + r];
        }
        __syncthreads();

        for (int icl = 0; icl < 8; icl++) {
#pragma unroll
            for (int ky = 0; ky < 8; ky++) {
                float iv[15];
#pragma unroll
                for (int j = 0; j < 15; j++) iv[j] = s_in[icl][row + ky][cs + j];
#pragma unroll
                for (int kx = 0; kx < 8; kx++) {
                    float wv = s_w[(oc*8 + icl)*64 + ky*8 + kx];
#pragma unroll
                    for (int j = 0; j < 8; j++) acc[j] += iv[kx + j] * wv;
                }
            }
        }
    }

    const float bs = bias[oc];
    const int oy = y0 + row;
    if (oy < HOUT) {
#pragma unroll
        for (int j = 0; j < 8; j++) {
            int ox = x0 + cs + j;
            if (ox < WOUT)
                out[(((long)b*16 + oc)*HOUT + oy)*WOUT + ox] = fmaxf(acc[j] + bs, 0.f);
        }
    }
}

// ===========================================================================
// conv4: 6x6 stride 2, (64,16,52,52) -> (64,16,24,24), +ReLU
// Block per (band of 6 out rows, b). IC chunked by 8.
// ===========================================================================
__global__ void conv4_kernel(const float* __restrict__ in,
                             const float* __restrict__ w,
                             const float* __restrict__ bias,
                             float* __restrict__ out) {
    __shared__ float s_in[8*16*52];   // 6656
    __shared__ float s_w[16*8*36];    // 4608
    const int band = blockIdx.x;      // 0..3
    const int b = blockIdx.y;
    const int tid = threadIdx.x;
    const int ry0 = band * 6;

    float acc[9];
#pragma unroll
    for (int t = 0; t < 9; t++) acc[t] = 0.f;

    for (int chunk = 0; chunk < 2; chunk++) {
        const int ic0 = chunk * 8;
        __syncthreads();
        for (int i = tid; i < 8*16*52; i += 256) {
            int icl = i / (16*52);
            int r = (i / 52) % 16, c = i % 52;
            s_in[i] = in[(((long)b*16 + ic0 + icl)*52 + 12*band + r)*52 + c];
        }
        for (int i = tid; i < 16*8*36; i += 256) {
            int o = i / (8*36);
            int r = i % (8*36);
            int icl = r / 36, k = r % 36;
            s_w[i] = w[(o*16 + ic0 + icl)*36 + k];
        }
        __syncthreads();
#pragma unroll
        for (int t = 0; t < 9; t++) {
            int task = tid + t*256;
            if (task < 2304) {
                int oc = task / 144;
                int r = task % 144;
                int row = r / 24, cx = r % 24;
                float a = acc[t];
                for (int icl = 0; icl < 8; icl++) {
#pragma unroll
                    for (int ky = 0; ky < 6; ky++) {
                        const float* rp = &s_in[(icl*16 + 2*row + ky)*52 + 2*cx];
                        const float* wpp = &s_w[(oc*8 + icl)*36 + ky*6];
#pragma unroll
                        for (int kx = 0; kx < 6; kx++) a += rp[kx] * wpp[kx];
                    }
                }
                acc[t] = a;
            }
        }
    }
#pragma unroll
    for (int t = 0; t < 9; t++) {
        int task = tid + t*256;
        if (task < 2304) {
            int oc = task / 144;
            int r = task % 144;
            int row = r / 24, cx = r % 24;
            out[(((long)b*16 + oc)*24 + ry0 + row)*24 + cx] = fmaxf(acc[t] + bias[oc], 0.f);
        }
    }
}

// ===========================================================================
// conv5: 5x5, (64,16,24,24) -> (64,16,20,20), +ReLU. All 16 ic in smem.
// Block per (band of 10 out rows, b).
// ===========================================================================
__global__ void conv5_kernel(const float* __restrict__ in,
                             const float* __restrict__ w,
                             const float* __restrict__ bias,
                             float* __restrict__ out) {
    __shared__ float s_in[16*14*24];  // 5376
    __shared__ float s_w[16*16*25];   // 6400
    const int band = blockIdx.x;      // 0..1
    const int b = blockIdx.y;
    const int tid = threadIdx.x;
    const int ry0 = band * 10;

    for (int i = tid; i < 16*14*24; i += 256) {
        int icl = i / (14*24);
        int r = (i / 24) % 14, c = i % 24;
        s_in[i] = in[(((long)b*16 + icl)*24 + ry0 + r)*24 + c];
    }
    for (int i = tid; i < 16*16*25; i += 256)
        s_w[i] = w[i];
    __syncthreads();

#pragma unroll
    for (int t = 0; t < 13; t++) {
        int task = tid + t*256;
        if (task < 3200) {
            int oc = task / 200;
            int r = task % 200;
            int row = r / 20, cx = r % 20;
            float a = 0.f;
            for (int ic = 0; ic < 16; ic++) {
#pragma unroll
                for (int ky = 0; ky < 5; ky++) {
                    const float* rp = &s_in[(ic*14 + row + ky)*24 + cx];
                    const float* wpp = &s_w[(oc*16 + ic)*25 + ky*5];
#pragma unroll
                    for (int kx = 0; kx < 5; kx++) a += rp[kx] * wpp[kx];
                }
            }
            out[(((long)b*16 + oc)*20 + ry0 + row)*20 + cx] = fmaxf(a + bias[oc], 0.f);
        }
    }
}

// ===========================================================================
// GEMM for fc1/fc2:  out(64,N) = relu(X(64,K) @ W(N,K)^T + b)
// Block tile 64(M) x 32(N), K-step 32, 256 threads, 4x2 micro-tile.
// ===========================================================================
__global__ void gemm_relu_kernel(const float* __restrict__ X,
                                 const float* __restrict__ W,
                                 const float* __restrict__ bias,
                                 float* __restrict__ out,
                                 int N, int K) {
    __shared__ float xs[32][65];
    __shared__ float ws[32][33];
    const int n0 = blockIdx.x * 32;
    const int tid = threadIdx.x;
    const int tx = tid & 15, ty = tid >> 4;

    float acc[4][2];
#pragma unroll
    for (int i = 0; i < 4; i++)
#pragma unroll
        for (int j = 0; j < 2; j++) acc[i][j] = 0.f;

    for (int k0 = 0; k0 < K; k0 += 32) {
        __syncthreads();
        for (int i = tid; i < 64*32; i += 256) {
            int m = i >> 5, k = i & 31;
            xs[k][m] = X[m*K + k0 + k];
        }
        for (int i = tid; i < 32*32; i += 256) {
            int n = i >> 5, k = i & 31;
            ws[k][n] = W[(long)(n0 + n)*K + k0 + k];
        }
        __syncthreads();
#pragma unroll
        for (int k = 0; k < 32; k++) {
            float a0 = xs[k][ty*4 + 0], a1 = xs[k][ty*4 + 1];
            float a2 = xs[k][ty*4 + 2], a3 = xs[k][ty*4 + 3];
            float b0 = ws[k][tx*2 + 0], b1 = ws[k][tx*2 + 1];
            acc[0][0] += a0*b0; acc[0][1] += a0*b1;
            acc[1][0] += a1*b0; acc[1][1] += a1*b1;
            acc[2][0] += a2*b0; acc[2][1] += a2*b1;
            acc[3][0] += a3*b0; acc[3][1] += a3*b1;
        }
    }
#pragma unroll
    for (int i = 0; i < 4; i++) {
        int m = ty*4 + i;
#pragma unroll
        for (int j = 0; j < 2; j++) {
            int n = n0 + tx*2 + j;
            out[m*N + n] = fmaxf(acc[i][j] + bias[n], 0.f);
        }
    }
}

// ===========================================================================
// fc3: (64,2048) @ (12,2048)^T + b -> (64,12).  One warp per output.
// ===========================================================================
__global__ void fc3_kernel(const float* __restrict__ X,
                           const float* __restrict__ W,
                           const float* __restrict__ bias,
                           float* __restrict__ out) {
    const int warp = (blockIdx.x * 256 + threadIdx.x) >> 5;
    const int lane = threadIdx.x & 31;
    if (warp >= 768) return;
    const int m = warp / 12, n = warp % 12;
    float s = 0.f;
    for (int k = lane; k < 2048; k += 32)
        s += X[m*2048 + k] * W[n*2048 + k];
#pragma unroll
    for (int o = 16; o; o >>= 1) s += __shfl_xor_sync(0xFFFFFFFFu, s, o);
    if (lane == 0) out[m*12 + n] = s + bias[n];
}

// ===========================================================================
extern "C" void kernel_launch(void* const* d_in, const int* in_sizes, int n_in,
                              void* d_out, int out_size) {
    const float* x       = (const float*)d_in[0];
    const float* conv1_w = (const float*)d_in[1];
    const float* conv1_b = (const float*)d_in[2];
    const float* rg_g    = (const float*)d_in[3];
    const float* rg_b    = (const float*)d_in[4];
    const float* rg_m    = (const float*)d_in[5];
    const float* rg_v    = (const float*)d_in[6];
    const float* rg_w    = (const float*)d_in[7];
    const float* rg_cb   = (const float*)d_in[8];
    const float* bn2_g   = (const float*)d_in[9];
    const float* bn2_b   = (const float*)d_in[10];
    const float* bn2_m   = (const float*)d_in[11];
    const float* bn2_v   = (const float*)d_in[12];
    const float* conv2_w = (const float*)d_in[13];
    const float* conv2_b = (const float*)d_in[14];
    const float* conv3_w = (const float*)d_in[15];
    const float* conv3_b = (const float*)d_in[16];
    const float* conv4_w = (const float*)d_in[17];
    const float* conv4_b = (const float*)d_in[18];
    const float* conv5_w = (const float*)d_in[19];
    const float* conv5_b = (const float*)d_in[20];
    const float* fc1_w   = (const float*)d_in[21];
    const float* fc1_b   = (const float*)d_in[22];
    const float* fc2_w   = (const float*)d_in[23];
    const float* fc2_b   = (const float*)d_in[24];
    const float* fc3_w   = (const float*)d_in[25];
    const float* fc3_b   = (const float*)d_in[26];

    float *b1, *b2, *b3, *b4, *b5, *b6, *f1, *f2;
    cudaGetSymbolAddress((void**)&b1, g_buf1);
    cudaGetSymbolAddress((void**)&b2, g_buf2);
    cudaGetSymbolAddress((void**)&b3, g_buf3);
    cudaGetSymbolAddress((void**)&b4, g_buf4);
    cudaGetSymbolAddress((void**)&b5, g_buf5);
    cudaGetSymbolAddress((void**)&b6, g_buf6);
    cudaGetSymbolAddress((void**)&f1, g_fc1o);
    cudaGetSymbolAddress((void**)&f2, g_fc2o);

    conv1_kernel<<<dim3(25, 4, 64), dim3(16, 16)>>>(x, conv1_w, conv1_b, b1);
    region_kernel<<<dim3(64, 64), 288>>>(b1, rg_g, rg_b, rg_m, rg_v, rg_w, rg_cb,
                                         bn2_g, bn2_b, bn2_m, bn2_v, b2);
    conv8x8_relu_kernel<32, 66, 66, 59, 59><<<dim3(4, 8, 64), 256>>>(b2, conv2_w, conv2_b, b3);
    conv8x8_relu_kernel<16, 59, 59, 52, 52><<<dim3(4, 7, 64), 256>>>(b3, conv3_w, conv3_b, b4);
    conv4_kernel<<<dim3(4, 64), 256>>>(b4, conv4_w, conv4_b, b5);
    conv5_kernel<<<dim3(2, 64), 256>>>(b5, conv5_w, conv5_b, b6);
    gemm_relu_kernel<<<128, 256>>>(b6, fc1_w, fc1_b, f1, 4096, 6400);
    gemm_relu_kernel<<<64, 256>>>(f1, fc2_w, fc2_b, f2, 2048, 4096);
    fc3_kernel<<<96, 256>>>(f2, fc3_w, fc3_b, (float*)d_out);
}

// round 2
// speedup vs baseline: 1.2329x; 1.2329x over previous
#include <cuda_runtime.h>
#include <cuda_bf16.h>

// ---------------- scratch buffers (static device globals; no allocation) ----
__device__ float g_buf1[64u*32u*132u*132u]; // conv1 out
__device__ float g_buf2[64u*32u*66u*66u];   // region+pool+bn2 out
__device__ float g_buf3[64u*16u*59u*59u];   // conv2 out
__device__ float g_buf4[64u*16u*52u*52u];   // conv3 out
__device__ float g_buf5[64u*16u*24u*24u];   // conv4 out
__device__ float g_buf6[64u*16u*20u*20u];   // conv5 out (fc input)
__device__ float g_fc1o[64u*4096u];
__device__ float g_fc2o[64u*2048u];

// ===========================================================================
// conv1: (64,3,142,142) -> (64,32,132,132), 11x11 VALID
// Exact tiling: 6 row-tiles of 22, 2 col-tiles of 66. Block = 264 threads.
// Thread: 11-px strip x 4 out channels. Per (c,ky): 65 LDS vs 484 FFMA.
// ===========================================================================
__global__ void __launch_bounds__(264, 2)
conv1_kernel(const float* __restrict__ x,
             const float* __restrict__ w,
             const float* __restrict__ bias,
             float* __restrict__ out) {
    __shared__ float s_in[3*32*76];   // 3 x (22+10) x (66+10)
    __shared__ float s_w[8*363];
    const int t   = blockIdx.x;       // 0..11
    const int ti  = t >> 1, tj = t & 1;
    const int gy0 = ti * 22, gx0 = tj * 66;
    const int ocg = blockIdx.y;       // 0..3 (8 oc each)
    const int b   = blockIdx.z;
    const int tid = threadIdx.x;

    for (int i = tid; i < 8*363; i += 264)
        s_w[i] = w[ocg*8*363 + i];
    for (int i = tid; i < 3*32*76; i += 264) {
        int c  = i / 2432;
        int r  = (i / 76) % 32, cc = i % 76;
        s_in[i] = x[((b*3 + c)*142 + gy0 + r)*142 + gx0 + cc];
    }
    __syncthreads();

    const int half = tid / 132;           // 0/1 -> oc sub-group
    const int s    = tid % 132;
    const int row  = s / 6;
    const int cs   = (s % 6) * 11;
    const int ocb  = half * 4;

    float acc[4][11];
#pragma unroll
    for (int o = 0; o < 4; o++)
#pragma unroll
        for (int j = 0; j < 11; j++) acc[o][j] = 0.f;

    for (int c = 0; c < 3; c++) {
        for (int ky = 0; ky < 11; ky++) {
            const float* ip = &s_in[c*2432 + (row + ky)*76 + cs];
            float iv[21];
#pragma unroll
            for (int j = 0; j < 21; j++) iv[j] = ip[j];
#pragma unroll
            for (int kx = 0; kx < 11; kx++) {
#pragma unroll
                for (int o = 0; o < 4; o++) {
                    float wv = s_w[(ocb + o)*363 + c*121 + ky*11 + kx];
#pragma unroll
                    for (int j = 0; j < 11; j++)
                        acc[o][j] += iv[kx + j] * wv;
                }
            }
        }
    }
#pragma unroll
    for (int o = 0; o < 4; o++) {
        const int oc = ocg*8 + ocb + o;
        const float bs = bias[oc];
        float* op = &out[(((long)b*32 + oc)*132 + gy0 + row)*132 + gx0 + cs];
#pragma unroll
        for (int j = 0; j < 11; j++) op[j] = acc[o][j] + bs;
    }
}

// ===========================================================================
// region layer fused: per-tile BN+ReLU -> 3x3 'same' conv -> +cb +residual
// -> ReLU -> maxpool2x2 -> BN2.  Block per (tile,b). 288 threads.
// Thread owns a 6x6 output patch of one oc (pos = tid/32 in up-to-3x3 grid).
// ===========================================================================
__global__ void __launch_bounds__(288)
region_kernel(const float* __restrict__ xin,
              const float* __restrict__ rg_g, const float* __restrict__ rg_b,
              const float* __restrict__ rg_m, const float* __restrict__ rg_v,
              const float* __restrict__ rg_w, const float* __restrict__ rg_cb,
              const float* __restrict__ bn2_g, const float* __restrict__ bn2_b,
              const float* __restrict__ bn2_m, const float* __restrict__ bn2_v,
              float* __restrict__ out) {
    __shared__ float smem[11008];  // s_in(6400)+s_w(4608) during conv; conv_out(<=10368) after
    __shared__ float s_scale[32], s_shift[32], s_cb[32], s_a2[32], s_b2[32];

    const int tile = blockIdx.x;
    const int b    = blockIdx.y;
    const int ti = tile >> 3, tj = tile & 7;
    const int th = (ti < 7) ? 18 : 6, tw = (tj < 7) ? 18 : 6;
    const int gy0 = ti * 18, gx0 = tj * 18;
    const int tid = threadIdx.x;

    if (tid < 32) {
        int p = tile*32 + tid;
        float a = rg_g[p] * rsqrtf(rg_v[p] + 1e-5f);
        s_scale[tid] = a;
        s_shift[tid] = rg_b[p] - rg_m[p]*a;
        s_cb[tid]    = rg_cb[p];
    } else if (tid < 64) {
        int c = tid - 32;
        float a2 = bn2_g[c] * rsqrtf(bn2_v[c] + 1e-5f);
        s_a2[c] = a2;
        s_b2[c] = bn2_b[c] - bn2_m[c]*a2;
    }

    const int hp = th + 2, wp = tw + 2;
    const int npx = tw / 6, npy = th / 6;
    const int pos = tid >> 5;
    const int oc  = tid & 31;
    const bool active = pos < npx * npy;
    const int prow = (pos / npx) * 6;     // valid when active
    const int pcol = (pos % npx) * 6;

    float* s_in = smem;
    float* s_w  = smem + 6400;

    float acc[6][6];
#pragma unroll
    for (int i = 0; i < 6; i++)
#pragma unroll
        for (int j = 0; j < 6; j++) acc[i][j] = 0.f;

    for (int chunk = 0; chunk < 2; chunk++) {
        const int ic0 = chunk * 16;
        __syncthreads();
        const int nin = 16 * hp * wp;
        for (int i = tid; i < nin; i += 288) {
            int icl = i / (hp*wp);
            int r = i % (hp*wp);
            int y = r / wp, xx = r % wp;
            float v = 0.f;
            if (y > 0 && y < hp-1 && xx > 0 && xx < wp-1) {
                float raw = xin[(((long)b*32 + ic0 + icl)*132 + gy0 + y - 1)*132 + gx0 + xx - 1];
                v = fmaxf(s_scale[ic0+icl]*raw + s_shift[ic0+icl], 0.f);
            }
            s_in[i] = v;
        }
        for (int i = tid; i < 32*16*9; i += 288) {
            int o = i / 144;
            int r = i % 144;
            s_w[i] = rg_w[(long)tile*9216 + o*288 + ic0*9 + r];
        }
        __syncthreads();

        if (active) {
            for (int icl = 0; icl < 16; icl++) {
                float wr[9];
#pragma unroll
                for (int k = 0; k < 9; k++) wr[k] = s_w[oc*144 + icl*9 + k];
                const float* ib = &s_in[icl*hp*wp + prow*wp + pcol];
#pragma unroll
                for (int r = 0; r < 8; r++) {
                    float iv[8];
#pragma unroll
                    for (int j = 0; j < 8; j++) iv[j] = ib[r*wp + j];
#pragma unroll
                    for (int ky = 0; ky < 3; ky++) {
                        int orow = r - ky;
                        if (orow >= 0 && orow < 6) {
#pragma unroll
                            for (int kx = 0; kx < 3; kx++) {
                                float wv = wr[ky*3 + kx];
#pragma unroll
                                for (int j = 0; j < 6; j++)
                                    acc[orow][j] += iv[kx + j] * wv;
                            }
                        }
                    }
                }
            }
        }
    }

    // stage conv results (+cb) into smem
    __syncthreads();
    if (active) {
        const float cb = s_cb[oc];
#pragma unroll
        for (int i = 0; i < 6; i++)
#pragma unroll
            for (int j = 0; j < 6; j++)
                smem[(oc*th + prow + i)*tw + pcol + j] = acc[i][j] + cb;
    }
    __syncthreads();

    // residual + relu + maxpool2x2 + bn2 (cooperative, coalesced-ish)
    const int ph = th / 2, pw = tw / 2;
    const int npool = 32 * ph * pw;
    for (int i = tid; i < npool; i += 288) {
        int c = i / (ph*pw);
        int r = i % (ph*pw);
        int py = r / pw, px = r % pw;
        const float* cp = &smem[(c*th + 2*py)*tw + 2*px];
        const float* rp = &xin[(((long)b*32 + c)*132 + gy0 + 2*py)*132 + gx0 + 2*px];
        float v00 = fmaxf(cp[0]    + rp[0],     0.f);
        float v01 = fmaxf(cp[1]    + rp[1],     0.f);
        float v10 = fmaxf(cp[tw]   + rp[132],   0.f);
        float v11 = fmaxf(cp[tw+1] + rp[133],   0.f);
        float m = fmaxf(fmaxf(v00, v01), fmaxf(v10, v11));
        out[(((long)b*32 + c)*66 + ti*9 + py)*66 + tj*9 + px] = s_a2[c]*m + s_b2[c];
    }
}

// ===========================================================================
// conv2 / conv3: 8x8 VALID, OC=16, +ReLU. Tile 8 rows x 32 cols, 256 thr.
// Thread: 1x8 strip x 2 ocs. Per (icl,ky): 31 LDS vs 128 FFMA.
// ===========================================================================
template<int CIN, int HIN, int WIN, int HOUT, int WOUT>
__global__ void __launch_bounds__(256)
conv8x8_relu_kernel(const float* __restrict__ in,
                    const float* __restrict__ w,
                    const float* __restrict__ bias,
                    float* __restrict__ out) {
    __shared__ float s_in[8*15*39];  // 4680
    __shared__ float s_w[16*8*64];   // 8192
    const int x0 = blockIdx.x * 32, y0 = blockIdx.y * 8;
    const int b = blockIdx.z;
    const int tid = threadIdx.x;
    const int oc0 = (tid >> 5) * 2;
    const int s   = tid & 31;
    const int row = s >> 2;
    const int cs  = (s & 3) * 8;

    float acc[2][8];
#pragma unroll
    for (int o = 0; o < 2; o++)
#pragma unroll
        for (int j = 0; j < 8; j++) acc[o][j] = 0.f;

    for (int chunk = 0; chunk < CIN/8; chunk++) {
        const int ic0 = chunk * 8;
        __syncthreads();
        for (int i = tid; i < 8*15*39; i += 256) {
            int icl = i / 585;
            int r = (i / 39) % 15, c = i % 39;
            int iy = y0 + r, ix = x0 + c;
            float v = 0.f;
            if (iy < HIN && ix < WIN)
                v = in[(((long)b*CIN + ic0 + icl)*HIN + iy)*WIN + ix];
            s_in[i] = v;
        }
        for (int i = tid; i < 16*8*64; i += 256) {
            int o = i >> 9;
            int r = i & 511;
            s_w[i] = w[o*CIN*64 + ic0*64 + r];
        }
        __syncthreads();

        for (int icl = 0; icl < 8; icl++) {
#pragma unroll
            for (int ky = 0; ky < 8; ky++) {
                const float* ip = &s_in[icl*585 + (row + ky)*39 + cs];
                float iv[15];
#pragma unroll
                for (int j = 0; j < 15; j++) iv[j] = ip[j];
#pragma unroll
                for (int kx = 0; kx < 8; kx++) {
                    float w0 = s_w[((oc0    )*8 + icl)*64 + ky*8 + kx];
                    float w1 = s_w[((oc0 + 1)*8 + icl)*64 + ky*8 + kx];
#pragma unroll
                    for (int j = 0; j < 8; j++) {
                        acc[0][j] += iv[kx + j] * w0;
                        acc[1][j] += iv[kx + j] * w1;
                    }
                }
            }
        }
    }

    const int oy = y0 + row;
    if (oy < HOUT) {
#pragma unroll
        for (int o = 0; o < 2; o++) {
            const float bs = bias[oc0 + o];
#pragma unroll
            for (int j = 0; j < 8; j++) {
                int ox = x0 + cs + j;
                if (ox < WOUT)
                    out[(((long)b*16 + oc0 + o)*HOUT + oy)*WOUT + ox] = fmaxf(acc[o][j] + bs, 0.f);
            }
        }
    }
}

// ===========================================================================
// conv4: 6x6 stride 2, (64,16,52,52) -> (64,16,24,24), +ReLU
// ===========================================================================
__global__ void conv4_kernel(const float* __restrict__ in,
                             const float* __restrict__ w,
                             const float* __restrict__ bias,
                             float* __restrict__ out) {
    __shared__ float s_in[8*16*52];
    __shared__ float s_w[16*8*36];
    const int band = blockIdx.x;      // 0..3
    const int b = blockIdx.y;
    const int tid = threadIdx.x;
    const int ry0 = band * 6;

    float acc[9];
#pragma unroll
    for (int t = 0; t < 9; t++) acc[t] = 0.f;

    for (int chunk = 0; chunk < 2; chunk++) {
        const int ic0 = chunk * 8;
        __syncthreads();
        for (int i = tid; i < 8*16*52; i += 256) {
            int icl = i / (16*52);
            int r = (i / 52) % 16, c = i % 52;
            s_in[i] = in[(((long)b*16 + ic0 + icl)*52 + 12*band + r)*52 + c];
        }
        for (int i = tid; i < 16*8*36; i += 256) {
            int o = i / (8*36);
            int r = i % (8*36);
            int icl = r / 36, k = r % 36;
            s_w[i] = w[(o*16 + ic0 + icl)*36 + k];
        }
        __syncthreads();
#pragma unroll
        for (int t = 0; t < 9; t++) {
            int task = tid + t*256;
            if (task < 2304) {
                int oc = task / 144;
                int r = task % 144;
                int row = r / 24, cx = r % 24;
                float a = acc[t];
                for (int icl = 0; icl < 8; icl++) {
#pragma unroll
                    for (int ky = 0; ky < 6; ky++) {
                        const float* rp = &s_in[(icl*16 + 2*row + ky)*52 + 2*cx];
                        const float* wpp = &s_w[(oc*8 + icl)*36 + ky*6];
#pragma unroll
                        for (int kx = 0; kx < 6; kx++) a += rp[kx] * wpp[kx];
                    }
                }
                acc[t] = a;
            }
        }
    }
#pragma unroll
    for (int t = 0; t < 9; t++) {
        int task = tid + t*256;
        if (task < 2304) {
            int oc = task / 144;
            int r = task % 144;
            int row = r / 24, cx = r % 24;
            out[(((long)b*16 + oc)*24 + ry0 + row)*24 + cx] = fmaxf(acc[t] + bias[oc], 0.f);
        }
    }
}

// ===========================================================================
// conv5: 5x5, (64,16,24,24) -> (64,16,20,20), +ReLU.
// ===========================================================================
__global__ void conv5_kernel(const float* __restrict__ in,
                             const float* __restrict__ w,
                             const float* __restrict__ bias,
                             float* __restrict__ out) {
    __shared__ float s_in[16*14*24];
    __shared__ float s_w[16*16*25];
    const int band = blockIdx.x;      // 0..1
    const int b = blockIdx.y;
    const int tid = threadIdx.x;
    const int ry0 = band * 10;

    for (int i = tid; i < 16*14*24; i += 256) {
        int icl = i / (14*24);
        int r = (i / 24) % 14, c = i % 24;
        s_in[i] = in[(((long)b*16 + icl)*24 + ry0 + r)*24 + c];
    }
    for (int i = tid; i < 16*16*25; i += 256)
        s_w[i] = w[i];
    __syncthreads();

#pragma unroll
    for (int t = 0; t < 13; t++) {
        int task = tid + t*256;
        if (task < 3200) {
            int oc = task / 200;
            int r = task % 200;
            int row = r / 20, cx = r % 20;
            float a = 0.f;
            for (int ic = 0; ic < 16; ic++) {
#pragma unroll
                for (int ky = 0; ky < 5; ky++) {
                    const float* rp = &s_in[(ic*14 + row + ky)*24 + cx];
                    const float* wpp = &s_w[(oc*16 + ic)*25 + ky*5];
#pragma unroll
                    for (int kx = 0; kx < 5; kx++) a += rp[kx] * wpp[kx];
                }
            }
            out[(((long)b*16 + oc)*20 + ry0 + row)*20 + cx] = fmaxf(a + bias[oc], 0.f);
        }
    }
}

// ===========================================================================
// GEMM for fc1/fc2:  out(64,N) = relu(X(64,K) @ W(N,K)^T + b)
// ===========================================================================
__global__ void gemm_relu_kernel(const float* __restrict__ X,
                                 const float* __restrict__ W,
                                 const float* __restrict__ bias,
                                 float* __restrict__ out,
                                 int N, int K) {
    __shared__ float xs[32][65];
    __shared__ float ws[32][33];
    const int n0 = blockIdx.x * 32;
    const int tid = threadIdx.x;
    const int tx = tid & 15, ty = tid >> 4;

    float acc[4][2];
#pragma unroll
    for (int i = 0; i < 4; i++)
#pragma unroll
        for (int j = 0; j < 2; j++) acc[i][j] = 0.f;

    for (int k0 = 0; k0 < K; k0 += 32) {
        __syncthreads();
        for (int i = tid; i < 64*32; i += 256) {
            int m = i >> 5, k = i & 31;
            xs[k][m] = X[m*K + k0 + k];
        }
        for (int i = tid; i < 32*32; i += 256) {
            int n = i >> 5, k = i & 31;
            ws[k][n] = W[(long)(n0 + n)*K + k0 + k];
        }
        __syncthreads();
#pragma unroll
        for (int k = 0; k < 32; k++) {
            float a0 = xs[k][ty*4 + 0], a1 = xs[k][ty*4 + 1];
            float a2 = xs[k][ty*4 + 2], a3 = xs[k][ty*4 + 3];
            float b0 = ws[k][tx*2 + 0], b1 = ws[k][tx*2 + 1];
            acc[0][0] += a0*b0; acc[0][1] += a0*b1;
            acc[1][0] += a1*b0; acc[1][1] += a1*b1;
            acc[2][0] += a2*b0; acc[2][1] += a2*b1;
            acc[3][0] += a3*b0; acc[3][1] += a3*b1;
        }
    }
#pragma unroll
    for (int i = 0; i < 4; i++) {
        int m = ty*4 + i;
#pragma unroll
        for (int j = 0; j < 2; j++) {
            int n = n0 + tx*2 + j;
            out[m*N + n] = fmaxf(acc[i][j] + bias[n], 0.f);
        }
    }
}

// ===========================================================================
// fc3: (64,2048) @ (12,2048)^T + b -> (64,12).  One warp per output.
// ===========================================================================
__global__ void fc3_kernel(const float* __restrict__ X,
                           const float* __restrict__ W,
                           const float* __restrict__ bias,
                           float* __restrict__ out) {
    const int warp = (blockIdx.x * 256 + threadIdx.x) >> 5;
    const int lane = threadIdx.x & 31;
    if (warp >= 768) return;
    const int m = warp / 12, n = warp % 12;
    float s = 0.f;
    for (int k = lane; k < 2048; k += 32)
        s += X[m*2048 + k] * W[n*2048 + k];
#pragma unroll
    for (int o = 16; o; o >>= 1) s += __shfl_xor_sync(0xFFFFFFFFu, s, o);
    if (lane == 0) out[m*12 + n] = s + bias[n];
}

// ===========================================================================
extern "C" void kernel_launch(void* const* d_in, const int* in_sizes, int n_in,
                              void* d_out, int out_size) {
    const float* x       = (const float*)d_in[0];
    const float* conv1_w = (const float*)d_in[1];
    const float* conv1_b = (const float*)d_in[2];
    const float* rg_g    = (const float*)d_in[3];
    const float* rg_b    = (const float*)d_in[4];
    const float* rg_m    = (const float*)d_in[5];
    const float* rg_v    = (const float*)d_in[6];
    const float* rg_w    = (const float*)d_in[7];
    const float* rg_cb   = (const float*)d_in[8];
    const float* bn2_g   = (const float*)d_in[9];
    const float* bn2_b   = (const float*)d_in[10];
    const float* bn2_m   = (const float*)d_in[11];
    const float* bn2_v   = (const float*)d_in[12];
    const float* conv2_w = (const float*)d_in[13];
    const float* conv2_b = (const float*)d_in[14];
    const float* conv3_w = (const float*)d_in[15];
    const float* conv3_b = (const float*)d_in[16];
    const float* conv4_w = (const float*)d_in[17];
    const float* conv4_b = (const float*)d_in[18];
    const float* conv5_w = (const float*)d_in[19];
    const float* conv5_b = (const float*)d_in[20];
    const float* fc1_w   = (const float*)d_in[21];
    const float* fc1_b   = (const float*)d_in[22];
    const float* fc2_w   = (const float*)d_in[23];
    const float* fc2_b   = (const float*)d_in[24];
    const float* fc3_w   = (const float*)d_in[25];
    const float* fc3_b   = (const float*)d_in[26];

    float *b1, *b2, *b3, *b4, *b5, *b6, *f1, *f2;
    cudaGetSymbolAddress((void**)&b1, g_buf1);
    cudaGetSymbolAddress((void**)&b2, g_buf2);
    cudaGetSymbolAddress((void**)&b3, g_buf3);
    cudaGetSymbolAddress((void**)&b4, g_buf4);
    cudaGetSymbolAddress((void**)&b5, g_buf5);
    cudaGetSymbolAddress((void**)&b6, g_buf6);
    cudaGetSymbolAddress((void**)&f1, g_fc1o);
    cudaGetSymbolAddress((void**)&f2, g_fc2o);

    conv1_kernel<<<dim3(12, 4, 64), 264>>>(x, conv1_w, conv1_b, b1);
    region_kernel<<<dim3(64, 64), 288>>>(b1, rg_g, rg_b, rg_m, rg_v, rg_w, rg_cb,
                                         bn2_g, bn2_b, bn2_m, bn2_v, b2);
    conv8x8_relu_kernel<32, 66, 66, 59, 59><<<dim3(2, 8, 64), 256>>>(b2, conv2_w, conv2_b, b3);
    conv8x8_relu_kernel<16, 59, 59, 52, 52><<<dim3(2, 7, 64), 256>>>(b3, conv3_w, conv3_b, b4);
    conv4_kernel<<<dim3(4, 64), 256>>>(b4, conv4_w, conv4_b, b5);
    conv5_kernel<<<dim3(2, 64), 256>>>(b5, conv5_w, conv5_b, b6);
    gemm_relu_kernel<<<128, 256>>>(b6, fc1_w, fc1_b, f1, 4096, 6400);
    gemm_relu_kernel<<<64, 256>>>(f1, fc2_w, fc2_b, f2, 2048, 4096);
    fc3_kernel<<<96, 256>>>(f2, fc3_w, fc3_b, (float*)d_out);
}

// round 3
// speedup vs baseline: 1.5197x; 1.2326x over previous
#include <cuda_runtime.h>
#include <cuda_bf16.h>

// ---------------- scratch buffers (static device globals; no allocation) ----
__device__ float g_buf1[64u*32u*132u*132u]; // conv1 out
__device__ float g_buf2[64u*32u*66u*66u];   // region+pool+bn2 out
__device__ float g_buf3[64u*16u*59u*59u];   // conv2 out
__device__ float g_buf4[64u*16u*52u*52u];   // conv3 out
__device__ float g_buf5[64u*16u*24u*24u];   // conv4 out
__device__ float g_buf6[64u*16u*20u*20u];   // conv5 out (fc input)
__device__ float g_fc1o[64u*4096u];
__device__ float g_fc2o[64u*2048u];

// ===========================================================================
// conv1: (64,3,142,142) -> (64,32,132,132), 11x11 VALID
// Tiling: 6 row-tiles of 22, 2 col-tiles of 66; 8 oc-groups of 4.
// Thread: 11-px strip x 2 out channels. Better occupancy than 4-oc variant.
// ===========================================================================
__global__ void __launch_bounds__(264, 3)
conv1_kernel(const float* __restrict__ x,
             const float* __restrict__ w,
             const float* __restrict__ bias,
             float* __restrict__ out) {
    __shared__ float s_in[3*32*76];   // 3 x (22+10) x (66+10)
    __shared__ float s_w[4*363];
    const int t   = blockIdx.x;       // 0..11
    const int ti  = t >> 1, tj = t & 1;
    const int gy0 = ti * 22, gx0 = tj * 66;
    const int ocg = blockIdx.y;       // 0..7 (4 oc each)
    const int b   = blockIdx.z;
    const int tid = threadIdx.x;

    for (int i = tid; i < 4*363; i += 264)
        s_w[i] = w[ocg*4*363 + i];
    for (int i = tid; i < 3*32*76; i += 264) {
        int c  = i / 2432;
        int r  = (i / 76) % 32, cc = i % 76;
        s_in[i] = x[((b*3 + c)*142 + gy0 + r)*142 + gx0 + cc];
    }
    __syncthreads();

    const int half = tid / 132;           // 0/1 -> oc pair
    const int s    = tid % 132;
    const int row  = s / 6;
    const int cs   = (s % 6) * 11;
    const int ocb  = half * 2;

    float acc[2][11];
#pragma unroll
    for (int o = 0; o < 2; o++)
#pragma unroll
        for (int j = 0; j < 11; j++) acc[o][j] = 0.f;

    for (int c = 0; c < 3; c++) {
        for (int ky = 0; ky < 11; ky++) {
            const float* ip = &s_in[c*2432 + (row + ky)*76 + cs];
            float iv[21];
#pragma unroll
            for (int j = 0; j < 21; j++) iv[j] = ip[j];
#pragma unroll
            for (int kx = 0; kx < 11; kx++) {
                float w0 = s_w[(ocb    )*363 + c*121 + ky*11 + kx];
                float w1 = s_w[(ocb + 1)*363 + c*121 + ky*11 + kx];
#pragma unroll
                for (int j = 0; j < 11; j++) {
                    acc[0][j] += iv[kx + j] * w0;
                    acc[1][j] += iv[kx + j] * w1;
                }
            }
        }
    }
#pragma unroll
    for (int o = 0; o < 2; o++) {
        const int oc = ocg*4 + ocb + o;
        const float bs = bias[oc];
        float* op = &out[(((long)b*32 + oc)*132 + gy0 + row)*132 + gx0 + cs];
#pragma unroll
        for (int j = 0; j < 11; j++) op[j] = acc[o][j] + bs;
    }
}

// ===========================================================================
// region layer fused: per-tile BN+ReLU -> 3x3 'same' conv -> +cb +residual
// -> ReLU -> maxpool2x2 -> BN2.  Block per (tile,b). 288 threads.
// ===========================================================================
__global__ void __launch_bounds__(288)
region_kernel(const float* __restrict__ xin,
              const float* __restrict__ rg_g, const float* __restrict__ rg_b,
              const float* __restrict__ rg_m, const float* __restrict__ rg_v,
              const float* __restrict__ rg_w, const float* __restrict__ rg_cb,
              const float* __restrict__ bn2_g, const float* __restrict__ bn2_b,
              const float* __restrict__ bn2_m, const float* __restrict__ bn2_v,
              float* __restrict__ out) {
    __shared__ float smem[11008];
    __shared__ float s_scale[32], s_shift[32], s_cb[32], s_a2[32], s_b2[32];

    const int tile = blockIdx.x;
    const int b    = blockIdx.y;
    const int ti = tile >> 3, tj = tile & 7;
    const int th = (ti < 7) ? 18 : 6, tw = (tj < 7) ? 18 : 6;
    const int gy0 = ti * 18, gx0 = tj * 18;
    const int tid = threadIdx.x;

    if (tid < 32) {
        int p = tile*32 + tid;
        float a = rg_g[p] * rsqrtf(rg_v[p] + 1e-5f);
        s_scale[tid] = a;
        s_shift[tid] = rg_b[p] - rg_m[p]*a;
        s_cb[tid]    = rg_cb[p];
    } else if (tid < 64) {
        int c = tid - 32;
        float a2 = bn2_g[c] * rsqrtf(bn2_v[c] + 1e-5f);
        s_a2[c] = a2;
        s_b2[c] = bn2_b[c] - bn2_m[c]*a2;
    }

    const int hp = th + 2, wp = tw + 2;
    const int npx = tw / 6, npy = th / 6;
    const int pos = tid >> 5;
    const int oc  = tid & 31;
    const bool active = pos < npx * npy;
    const int prow = (pos / npx) * 6;
    const int pcol = (pos % npx) * 6;

    float* s_in = smem;
    float* s_w  = smem + 6400;

    float acc[6][6];
#pragma unroll
    for (int i = 0; i < 6; i++)
#pragma unroll
        for (int j = 0; j < 6; j++) acc[i][j] = 0.f;

    for (int chunk = 0; chunk < 2; chunk++) {
        const int ic0 = chunk * 16;
        __syncthreads();
        const int nin = 16 * hp * wp;
        for (int i = tid; i < nin; i += 288) {
            int icl = i / (hp*wp);
            int r = i % (hp*wp);
            int y = r / wp, xx = r % wp;
            float v = 0.f;
            if (y > 0 && y < hp-1 && xx > 0 && xx < wp-1) {
                float raw = xin[(((long)b*32 + ic0 + icl)*132 + gy0 + y - 1)*132 + gx0 + xx - 1];
                v = fmaxf(s_scale[ic0+icl]*raw + s_shift[ic0+icl], 0.f);
            }
            s_in[i] = v;
        }
        for (int i = tid; i < 32*16*9; i += 288) {
            int o = i / 144;
            int r = i % 144;
            s_w[i] = rg_w[(long)tile*9216 + o*288 + ic0*9 + r];
        }
        __syncthreads();

        if (active) {
            for (int icl = 0; icl < 16; icl++) {
                float wr[9];
#pragma unroll
                for (int k = 0; k < 9; k++) wr[k] = s_w[oc*144 + icl*9 + k];
                const float* ib = &s_in[icl*hp*wp + prow*wp + pcol];
#pragma unroll
                for (int r = 0; r < 8; r++) {
                    float iv[8];
#pragma unroll
                    for (int j = 0; j < 8; j++) iv[j] = ib[r*wp + j];
#pragma unroll
                    for (int ky = 0; ky < 3; ky++) {
                        int orow = r - ky;
                        if (orow >= 0 && orow < 6) {
#pragma unroll
                            for (int kx = 0; kx < 3; kx++) {
                                float wv = wr[ky*3 + kx];
#pragma unroll
                                for (int j = 0; j < 6; j++)
                                    acc[orow][j] += iv[kx + j] * wv;
                            }
                        }
                    }
                }
            }
        }
    }

    __syncthreads();
    if (active) {
        const float cb = s_cb[oc];
#pragma unroll
        for (int i = 0; i < 6; i++)
#pragma unroll
            for (int j = 0; j < 6; j++)
                smem[(oc*th + prow + i)*tw + pcol + j] = acc[i][j] + cb;
    }
    __syncthreads();

    const int ph = th / 2, pw = tw / 2;
    const int npool = 32 * ph * pw;
    for (int i = tid; i < npool; i += 288) {
        int c = i / (ph*pw);
        int r = i % (ph*pw);
        int py = r / pw, px = r % pw;
        const float* cp = &smem[(c*th + 2*py)*tw + 2*px];
        const float* rp = &xin[(((long)b*32 + c)*132 + gy0 + 2*py)*132 + gx0 + 2*px];
        float v00 = fmaxf(cp[0]    + rp[0],     0.f);
        float v01 = fmaxf(cp[1]    + rp[1],     0.f);
        float v10 = fmaxf(cp[tw]   + rp[132],   0.f);
        float v11 = fmaxf(cp[tw+1] + rp[133],   0.f);
        float m = fmaxf(fmaxf(v00, v01), fmaxf(v10, v11));
        out[(((long)b*32 + c)*66 + ti*9 + py)*66 + tj*9 + px] = s_a2[c]*m + s_b2[c];
    }
}

// ===========================================================================
// conv2 / conv3: 8x8 VALID, OC=16, +ReLU. Tile 8 rows x 32 cols, 256 thr.
// Thread: 1x8 strip x 2 ocs. Vectorized smem: 8 LDS.128 per 128 FFMA.
// ===========================================================================
template<int CIN, int HIN, int WIN, int HOUT, int WOUT>
__global__ void __launch_bounds__(256, 3)
conv8x8_relu_kernel(const float* __restrict__ in,
                    const float* __restrict__ w,
                    const float* __restrict__ bias,
                    float* __restrict__ out) {
    __shared__ float s_in[8*15*40];  // padded rows (40) for float4 alignment
    __shared__ float s_w[16*8*64];   // 8192
    const int x0 = blockIdx.x * 32, y0 = blockIdx.y * 8;
    const int b = blockIdx.z;
    const int tid = threadIdx.x;
    const int oc0 = (tid >> 5) * 2;
    const int s   = tid & 31;
    const int row = s >> 2;
    const int cs  = (s & 3) * 8;

    float acc[2][8];
#pragma unroll
    for (int o = 0; o < 2; o++)
#pragma unroll
        for (int j = 0; j < 8; j++) acc[o][j] = 0.f;

    for (int chunk = 0; chunk < CIN/8; chunk++) {
        const int ic0 = chunk * 8;
        __syncthreads();
        for (int i = tid; i < 8*15*40; i += 256) {
            int icl = i / 600;
            int r = (i / 40) % 15, c = i % 40;
            int iy = y0 + r, ix = x0 + c;
            float v = 0.f;
            if (c < 39 && iy < HIN && ix < WIN)
                v = in[(((long)b*CIN + ic0 + icl)*HIN + iy)*WIN + ix];
            s_in[i] = v;
        }
        for (int i = tid; i < 16*8*64; i += 256) {
            int o = i >> 9;
            int r = i & 511;
            s_w[i] = w[o*CIN*64 + ic0*64 + r];
        }
        __syncthreads();

        for (int icl = 0; icl < 8; icl++) {
#pragma unroll
            for (int ky = 0; ky < 8; ky++) {
                const float* ip = &s_in[icl*600 + (row + ky)*40 + cs];
                float4 v0 = *(const float4*)(ip);
                float4 v1 = *(const float4*)(ip + 4);
                float4 v2 = *(const float4*)(ip + 8);
                float4 v3 = *(const float4*)(ip + 12);
                float iv[16];
                iv[0]=v0.x; iv[1]=v0.y; iv[2]=v0.z; iv[3]=v0.w;
                iv[4]=v1.x; iv[5]=v1.y; iv[6]=v1.z; iv[7]=v1.w;
                iv[8]=v2.x; iv[9]=v2.y; iv[10]=v2.z; iv[11]=v2.w;
                iv[12]=v3.x; iv[13]=v3.y; iv[14]=v3.z; iv[15]=v3.w;
                const float4* wp0 = (const float4*)&s_w[((oc0    )*8 + icl)*64 + ky*8];
                const float4* wp1 = (const float4*)&s_w[((oc0 + 1)*8 + icl)*64 + ky*8];
                float4 wa0 = wp0[0], wb0 = wp0[1];
                float4 wa1 = wp1[0], wb1 = wp1[1];
                float w0[8], w1[8];
                w0[0]=wa0.x; w0[1]=wa0.y; w0[2]=wa0.z; w0[3]=wa0.w;
                w0[4]=wb0.x; w0[5]=wb0.y; w0[6]=wb0.z; w0[7]=wb0.w;
                w1[0]=wa1.x; w1[1]=wa1.y; w1[2]=wa1.z; w1[3]=wa1.w;
                w1[4]=wb1.x; w1[5]=wb1.y; w1[6]=wb1.z; w1[7]=wb1.w;
#pragma unroll
                for (int kx = 0; kx < 8; kx++) {
#pragma unroll
                    for (int j = 0; j < 8; j++) {
                        acc[0][j] += iv[kx + j] * w0[kx];
                        acc[1][j] += iv[kx + j] * w1[kx];
                    }
                }
            }
        }
    }

    const int oy = y0 + row;
    if (oy < HOUT) {
#pragma unroll
        for (int o = 0; o < 2; o++) {
            const float bs = bias[oc0 + o];
#pragma unroll
            for (int j = 0; j < 8; j++) {
                int ox = x0 + cs + j;
                if (ox < WOUT)
                    out[(((long)b*16 + oc0 + o)*HOUT + oy)*WOUT + ox] = fmaxf(acc[o][j] + bs, 0.f);
            }
        }
    }
}

// ===========================================================================
// conv4: 6x6 stride 2, (64,16,52,52) -> (64,16,24,24), +ReLU
// ===========================================================================
__global__ void conv4_kernel(const float* __restrict__ in,
                             const float* __restrict__ w,
                             const float* __restrict__ bias,
                             float* __restrict__ out) {
    __shared__ float s_in[8*16*52];
    __shared__ float s_w[16*8*36];
    const int band = blockIdx.x;
    const int b = blockIdx.y;
    const int tid = threadIdx.x;
    const int ry0 = band * 6;

    float acc[9];
#pragma unroll
    for (int t = 0; t < 9; t++) acc[t] = 0.f;

    for (int chunk = 0; chunk < 2; chunk++) {
        const int ic0 = chunk * 8;
        __syncthreads();
        for (int i = tid; i < 8*16*52; i += 256) {
            int icl = i / (16*52);
            int r = (i / 52) % 16, c = i % 52;
            s_in[i] = in[(((long)b*16 + ic0 + icl)*52 + 12*band + r)*52 + c];
        }
        for (int i = tid; i < 16*8*36; i += 256) {
            int o = i / (8*36);
            int r = i % (8*36);
            int icl = r / 36, k = r % 36;
            s_w[i] = w[(o*16 + ic0 + icl)*36 + k];
        }
        __syncthreads();
#pragma unroll
        for (int t = 0; t < 9; t++) {
            int task = tid + t*256;
            if (task < 2304) {
                int oc = task / 144;
                int r = task % 144;
                int row = r / 24, cx = r % 24;
                float a = acc[t];
                for (int icl = 0; icl < 8; icl++) {
#pragma unroll
                    for (int ky = 0; ky < 6; ky++) {
                        const float* rp = &s_in[(icl*16 + 2*row + ky)*52 + 2*cx];
                        const float* wpp = &s_w[(oc*8 + icl)*36 + ky*6];
#pragma unroll
                        for (int kx = 0; kx < 6; kx++) a += rp[kx] * wpp[kx];
                    }
                }
                acc[t] = a;
            }
        }
    }
#pragma unroll
    for (int t = 0; t < 9; t++) {
        int task = tid + t*256;
        if (task < 2304) {
            int oc = task / 144;
            int r = task % 144;
            int row = r / 24, cx = r % 24;
            out[(((long)b*16 + oc)*24 + ry0 + row)*24 + cx] = fmaxf(acc[t] + bias[oc], 0.f);
        }
    }
}

// ===========================================================================
// conv5: 5x5, (64,16,24,24) -> (64,16,20,20), +ReLU.
// ===========================================================================
__global__ void conv5_kernel(const float* __restrict__ in,
                             const float* __restrict__ w,
                             const float* __restrict__ bias,
                             float* __restrict__ out) {
    __shared__ float s_in[16*14*24];
    __shared__ float s_w[16*16*25];
    const int band = blockIdx.x;
    const int b = blockIdx.y;
    const int tid = threadIdx.x;
    const int ry0 = band * 10;

    for (int i = tid; i < 16*14*24; i += 256) {
        int icl = i / (14*24);
        int r = (i / 24) % 14, c = i % 24;
        s_in[i] = in[(((long)b*16 + icl)*24 + ry0 + r)*24 + c];
    }
    for (int i = tid; i < 16*16*25; i += 256)
        s_w[i] = w[i];
    __syncthreads();

#pragma unroll
    for (int t = 0; t < 13; t++) {
        int task = tid + t*256;
        if (task < 3200) {
            int oc = task / 200;
            int r = task % 200;
            int row = r / 20, cx = r % 20;
            float a = 0.f;
            for (int ic = 0; ic < 16; ic++) {
#pragma unroll
                for (int ky = 0; ky < 5; ky++) {
                    const float* rp = &s_in[(ic*14 + row + ky)*24 + cx];
                    const float* wpp = &s_w[(oc*16 + ic)*25 + ky*5];
#pragma unroll
                    for (int kx = 0; kx < 5; kx++) a += rp[kx] * wpp[kx];
                }
            }
            out[(((long)b*16 + oc)*20 + ry0 + row)*20 + cx] = fmaxf(a + bias[oc], 0.f);
        }
    }
}

// ===========================================================================
// GEMM for fc1/fc2:  out(64,N) = relu(X(64,K) @ W(N,K)^T + b)
// Block tile 64(M) x 64(N), K-panel 64, 256 threads, 4x4 micro-tile,
// float4 LDS -> 2 LDS per 16 FFMA.
// ===========================================================================
__global__ void __launch_bounds__(256)
gemm_relu_kernel(const float* __restrict__ X,
                 const float* __restrict__ W,
                 const float* __restrict__ bias,
                 float* __restrict__ out,
                 int N, int K) {
    __shared__ float xs[64][68];
    __shared__ float ws[64][68];
    const int n0 = blockIdx.x * 64;
    const int tid = threadIdx.x;
    const int tx = tid & 15, ty = tid >> 4;

    float acc[4][4];
#pragma unroll
    for (int i = 0; i < 4; i++)
#pragma unroll
        for (int j = 0; j < 4; j++) acc[i][j] = 0.f;

    for (int k0 = 0; k0 < K; k0 += 64) {
        __syncthreads();
        for (int i = tid; i < 64*64; i += 256) {
            int m = i >> 6, k = i & 63;
            xs[k][m] = X[m*K + k0 + k];
        }
        for (int i = tid; i < 64*64; i += 256) {
            int n = i >> 6, k = i & 63;
            ws[k][n] = W[(long)(n0 + n)*K + k0 + k];
        }
        __syncthreads();
#pragma unroll 8
        for (int k = 0; k < 64; k++) {
            float4 a4 = *(const float4*)&xs[k][ty*4];
            float4 b4 = *(const float4*)&ws[k][tx*4];
            float a[4] = {a4.x, a4.y, a4.z, a4.w};
            float bb[4] = {b4.x, b4.y, b4.z, b4.w};
#pragma unroll
            for (int i = 0; i < 4; i++)
#pragma unroll
                for (int j = 0; j < 4; j++)
                    acc[i][j] += a[i] * bb[j];
        }
    }
#pragma unroll
    for (int i = 0; i < 4; i++) {
        int m = ty*4 + i;
#pragma unroll
        for (int j = 0; j < 4; j++) {
            int n = n0 + tx*4 + j;
            out[m*N + n] = fmaxf(acc[i][j] + bias[n], 0.f);
        }
    }
}

// ===========================================================================
// fc3: (64,2048) @ (12,2048)^T + b -> (64,12).  One warp per output.
// ===========================================================================
__global__ void fc3_kernel(const float* __restrict__ X,
                           const float* __restrict__ W,
                           const float* __restrict__ bias,
                           float* __restrict__ out) {
    const int warp = (blockIdx.x * 256 + threadIdx.x) >> 5;
    const int lane = threadIdx.x & 31;
    if (warp >= 768) return;
    const int m = warp / 12, n = warp % 12;
    float s = 0.f;
    for (int k = lane; k < 2048; k += 32)
        s += X[m*2048 + k] * W[n*2048 + k];
#pragma unroll
    for (int o = 16; o; o >>= 1) s += __shfl_xor_sync(0xFFFFFFFFu, s, o);
    if (lane == 0) out[m*12 + n] = s + bias[n];
}

// ===========================================================================
extern "C" void kernel_launch(void* const* d_in, const int* in_sizes, int n_in,
                              void* d_out, int out_size) {
    const float* x       = (const float*)d_in[0];
    const float* conv1_w = (const float*)d_in[1];
    const float* conv1_b = (const float*)d_in[2];
    const float* rg_g    = (const float*)d_in[3];
    const float* rg_b    = (const float*)d_in[4];
    const float* rg_m    = (const float*)d_in[5];
    const float* rg_v    = (const float*)d_in[6];
    const float* rg_w    = (const float*)d_in[7];
    const float* rg_cb   = (const float*)d_in[8];
    const float* bn2_g   = (const float*)d_in[9];
    const float* bn2_b   = (const float*)d_in[10];
    const float* bn2_m   = (const float*)d_in[11];
    const float* bn2_v   = (const float*)d_in[12];
    const float* conv2_w = (const float*)d_in[13];
    const float* conv2_b = (const float*)d_in[14];
    const float* conv3_w = (const float*)d_in[15];
    const float* conv3_b = (const float*)d_in[16];
    const float* conv4_w = (const float*)d_in[17];
    const float* conv4_b = (const float*)d_in[18];
    const float* conv5_w = (const float*)d_in[19];
    const float* conv5_b = (const float*)d_in[20];
    const float* fc1_w   = (const float*)d_in[21];
    const float* fc1_b   = (const float*)d_in[22];
    const float* fc2_w   = (const float*)d_in[23];
    const float* fc2_b   = (const float*)d_in[24];
    const float* fc3_w   = (const float*)d_in[25];
    const float* fc3_b   = (const float*)d_in[26];

    float *b1, *b2, *b3, *b4, *b5, *b6, *f1, *f2;
    cudaGetSymbolAddress((void**)&b1, g_buf1);
    cudaGetSymbolAddress((void**)&b2, g_buf2);
    cudaGetSymbolAddress((void**)&b3, g_buf3);
    cudaGetSymbolAddress((void**)&b4, g_buf4);
    cudaGetSymbolAddress((void**)&b5, g_buf5);
    cudaGetSymbolAddress((void**)&b6, g_buf6);
    cudaGetSymbolAddress((void**)&f1, g_fc1o);
    cudaGetSymbolAddress((void**)&f2, g_fc2o);

    conv1_kernel<<<dim3(12, 8, 64), 264>>>(x, conv1_w, conv1_b, b1);
    region_kernel<<<dim3(64, 64), 288>>>(b1, rg_g, rg_b, rg_m, rg_v, rg_w, rg_cb,
                                         bn2_g, bn2_b, bn2_m, bn2_v, b2);
    conv8x8_relu_kernel<32, 66, 66, 59, 59><<<dim3(2, 8, 64), 256>>>(b2, conv2_w, conv2_b, b3);
    conv8x8_relu_kernel<16, 59, 59, 52, 52><<<dim3(2, 7, 64), 256>>>(b3, conv3_w, conv3_b, b4);
    conv4_kernel<<<dim3(4, 64), 256>>>(b4, conv4_w, conv4_b, b5);
    conv5_kernel<<<dim3(2, 64), 256>>>(b5, conv5_w, conv5_b, b6);
    gemm_relu_kernel<<<64, 256>>>(b6, fc1_w, fc1_b, f1, 4096, 6400);
    gemm_relu_kernel<<<32, 256>>>(f1, fc2_w, fc2_b, f2, 2048, 4096);
    fc3_kernel<<<96, 256>>>(f2, fc3_w, fc3_b, (float*)d_out);
}

// round 4
// speedup vs baseline: 1.5330x; 1.0088x over previous
#include <cuda_runtime.h>
#include <cuda_bf16.h>

typedef unsigned long long ull;

// ---- packed f32x2 helpers (sm_100+: one issue slot = two fp32 FMAs) ------
__device__ __forceinline__ ull pk2(float lo, float hi) {
    ull r; asm("mov.b64 %0, {%1, %2};" : "=l"(r) : "f"(lo), "f"(hi)); return r;
}
__device__ __forceinline__ ull bc2(float v) { return pk2(v, v); }
__device__ __forceinline__ void ffma2(ull& d, ull a, ull b) {
    asm("fma.rn.f32x2 %0, %1, %2, %3;" : "=l"(d) : "l"(a), "l"(b), "l"(d));
}
__device__ __forceinline__ float2 up2(ull v) {
    float2 f; asm("mov.b64 {%0, %1}, %2;" : "=f"(f.x), "=f"(f.y) : "l"(v)); return f;
}

// ---------------- scratch buffers (static device globals; no allocation) ----
__device__ float g_buf1[64u*32u*132u*132u]; // conv1 out
__device__ float g_buf2[64u*32u*66u*66u];   // region+pool+bn2 out
__device__ float g_buf3[64u*16u*59u*59u];   // conv2 out
__device__ float g_buf4[64u*16u*52u*52u];   // conv3 out
__device__ float g_buf5[64u*16u*24u*24u];   // conv4 out
__device__ float g_buf6[64u*16u*20u*20u];   // conv5 out (fc input)
__device__ float g_fc1o[64u*4096u];
__device__ float g_fc2o[64u*2048u];

// ===========================================================================
// conv1: (64,3,142,142) -> (64,32,132,132), 11x11 VALID
// f32x2: pack 2 out-channels per thread; weights interleaved float2 in smem.
// ===========================================================================
__global__ void __launch_bounds__(264, 2)
conv1_kernel(const float* __restrict__ x,
             const float* __restrict__ w,
             const float* __restrict__ bias,
             float* __restrict__ out) {
    __shared__ float  s_in[3*32*76];   // 3 x (22+10) x (66+10)
    __shared__ float2 s_w2[2*363];     // [half][c*121+ky*11+kx] = (w_oc, w_oc+1)
    const int t   = blockIdx.x;        // 0..11
    const int ti  = t >> 1, tj = t & 1;
    const int gy0 = ti * 22, gx0 = tj * 66;
    const int ocg = blockIdx.y;        // 0..7 (4 oc each)
    const int b   = blockIdx.z;
    const int tid = threadIdx.x;

    for (int i = tid; i < 2*363; i += 264) {
        int h = i / 363, idx = i % 363;
        int oc = ocg*4 + h*2;
        s_w2[i] = make_float2(w[oc*363 + idx], w[(oc+1)*363 + idx]);
    }
    for (int i = tid; i < 3*32*76; i += 264) {
        int c  = i / 2432;
        int r  = (i / 76) % 32, cc = i % 76;
        s_in[i] = x[((b*3 + c)*142 + gy0 + r)*142 + gx0 + cc];
    }
    __syncthreads();

    const int half = tid / 132;           // 0/1 -> oc pair
    const int s    = tid % 132;
    const int row  = s / 6;
    const int cs   = (s % 6) * 11;

    ull acc2[11];
#pragma unroll
    for (int j = 0; j < 11; j++) acc2[j] = 0ull;

    for (int c = 0; c < 3; c++) {
        for (int ky = 0; ky < 11; ky++) {
            const float* ip = &s_in[c*2432 + (row + ky)*76 + cs];
            ull ivb[21];
#pragma unroll
            for (int j = 0; j < 21; j++) ivb[j] = bc2(ip[j]);
            const float2* wrow = &s_w2[half*363 + c*121 + ky*11];
#pragma unroll
            for (int kx = 0; kx < 11; kx++) {
                ull w2 = *(const ull*)&wrow[kx];
#pragma unroll
                for (int j = 0; j < 11; j++)
                    ffma2(acc2[j], ivb[kx + j], w2);
            }
        }
    }
    const int oc = ocg*4 + half*2;
    const float b0 = bias[oc], b1 = bias[oc+1];
    float* o0 = &out[(((long)b*32 + oc)*132 + gy0 + row)*132 + gx0 + cs];
    float* o1 = o0 + 132*132;
#pragma unroll
    for (int j = 0; j < 11; j++) {
        float2 f = up2(acc2[j]);
        o0[j] = f.x + b0;
        o1[j] = f.y + b1;
    }
}

// ===========================================================================
// region layer fused: per-tile BN+ReLU -> 3x3 'same' conv -> +cb +residual
// -> ReLU -> maxpool2x2 -> BN2.  Block per (tile,b). 288 threads.
// f32x2: pack adjacent output columns (weight broadcast-packed).
// ===========================================================================
__global__ void __launch_bounds__(288)
region_kernel(const float* __restrict__ xin,
              const float* __restrict__ rg_g, const float* __restrict__ rg_b,
              const float* __restrict__ rg_m, const float* __restrict__ rg_v,
              const float* __restrict__ rg_w, const float* __restrict__ rg_cb,
              const float* __restrict__ bn2_g, const float* __restrict__ bn2_b,
              const float* __restrict__ bn2_m, const float* __restrict__ bn2_v,
              float* __restrict__ out) {
    __shared__ float smem[11008];
    __shared__ float s_scale[32], s_shift[32], s_cb[32], s_a2[32], s_b2[32];

    const int tile = blockIdx.x;
    const int b    = blockIdx.y;
    const int ti = tile >> 3, tj = tile & 7;
    const int th = (ti < 7) ? 18 : 6, tw = (tj < 7) ? 18 : 6;
    const int gy0 = ti * 18, gx0 = tj * 18;
    const int tid = threadIdx.x;

    if (tid < 32) {
        int p = tile*32 + tid;
        float a = rg_g[p] * rsqrtf(rg_v[p] + 1e-5f);
        s_scale[tid] = a;
        s_shift[tid] = rg_b[p] - rg_m[p]*a;
        s_cb[tid]    = rg_cb[p];
    } else if (tid < 64) {
        int c = tid - 32;
        float a2 = bn2_g[c] * rsqrtf(bn2_v[c] + 1e-5f);
        s_a2[c] = a2;
        s_b2[c] = bn2_b[c] - bn2_m[c]*a2;
    }

    const int hp = th + 2, wp = tw + 2;
    const int npx = tw / 6, npy = th / 6;
    const int pos = tid >> 5;
    const int oc  = tid & 31;
    const bool active = pos < npx * npy;
    const int prow = (pos / npx) * 6;
    const int pcol = (pos % npx) * 6;

    float* s_in = smem;
    float* s_w  = smem + 6400;

    ull acc2[6][3];
#pragma unroll
    for (int i = 0; i < 6; i++)
#pragma unroll
        for (int j = 0; j < 3; j++) acc2[i][j] = 0ull;

    for (int chunk = 0; chunk < 2; chunk++) {
        const int ic0 = chunk * 16;
        __syncthreads();
        const int nin = 16 * hp * wp;
        for (int i = tid; i < nin; i += 288) {
            int icl = i / (hp*wp);
            int r = i % (hp*wp);
            int y = r / wp, xx = r % wp;
            float v = 0.f;
            if (y > 0 && y < hp-1 && xx > 0 && xx < wp-1) {
                float raw = xin[(((long)b*32 + ic0 + icl)*132 + gy0 + y - 1)*132 + gx0 + xx - 1];
                v = fmaxf(s_scale[ic0+icl]*raw + s_shift[ic0+icl], 0.f);
            }
            s_in[i] = v;
        }
        for (int i = tid; i < 32*16*9; i += 288) {
            int o = i / 144;
            int r = i % 144;
            s_w[i] = rg_w[(long)tile*9216 + o*288 + ic0*9 + r];
        }
        __syncthreads();

        if (active) {
            for (int icl = 0; icl < 16; icl++) {
                ull wr2[9];
#pragma unroll
                for (int k = 0; k < 9; k++) wr2[k] = bc2(s_w[oc*144 + icl*9 + k]);
                const float* ib = &s_in[icl*hp*wp + prow*wp + pcol];
#pragma unroll
                for (int r = 0; r < 8; r++) {
                    float iv[8];
#pragma unroll
                    for (int j = 0; j < 8; j++) iv[j] = ib[r*wp + j];
                    ull p[7];
#pragma unroll
                    for (int i = 0; i < 7; i++) p[i] = pk2(iv[i], iv[i+1]);
#pragma unroll
                    for (int ky = 0; ky < 3; ky++) {
                        int orow = r - ky;
                        if (orow >= 0 && orow < 6) {
#pragma unroll
                            for (int kx = 0; kx < 3; kx++) {
                                ull w2 = wr2[ky*3 + kx];
                                ffma2(acc2[orow][0], p[kx    ], w2);
                                ffma2(acc2[orow][1], p[kx + 2], w2);
                                ffma2(acc2[orow][2], p[kx + 4], w2);
                            }
                        }
                    }
                }
            }
        }
    }

    __syncthreads();
    if (active) {
        const float cb = s_cb[oc];
#pragma unroll
        for (int i = 0; i < 6; i++)
#pragma unroll
            for (int jp = 0; jp < 3; jp++) {
                float2 f = up2(acc2[i][jp]);
                smem[(oc*th + prow + i)*tw + pcol + 2*jp    ] = f.x + cb;
                smem[(oc*th + prow + i)*tw + pcol + 2*jp + 1] = f.y + cb;
            }
    }
    __syncthreads();

    const int ph = th / 2, pw = tw / 2;
    const int npool = 32 * ph * pw;
    for (int i = tid; i < npool; i += 288) {
        int c = i / (ph*pw);
        int r = i % (ph*pw);
        int py = r / pw, px = r % pw;
        const float* cp = &smem[(c*th + 2*py)*tw + 2*px];
        const float* rp = &xin[(((long)b*32 + c)*132 + gy0 + 2*py)*132 + gx0 + 2*px];
        float v00 = fmaxf(cp[0]    + rp[0],     0.f);
        float v01 = fmaxf(cp[1]    + rp[1],     0.f);
        float v10 = fmaxf(cp[tw]   + rp[132],   0.f);
        float v11 = fmaxf(cp[tw+1] + rp[133],   0.f);
        float m = fmaxf(fmaxf(v00, v01), fmaxf(v10, v11));
        out[(((long)b*32 + c)*66 + ti*9 + py)*66 + tj*9 + px] = s_a2[c]*m + s_b2[c];
    }
}

// ===========================================================================
// conv2 / conv3: 8x8 VALID, OC=16, +ReLU. Tile 8 rows x 32 cols, 256 thr.
// f32x2: pack 2 ocs per thread; weights pre-interleaved float2 in smem.
// ===========================================================================
template<int CIN, int HIN, int WIN, int HOUT, int WOUT>
__global__ void __launch_bounds__(256, 2)
conv8x8_relu_kernel(const float* __restrict__ in,
                    const float* __restrict__ w,
                    const float* __restrict__ bias,
                    float* __restrict__ out) {
    __shared__ float  s_in[8*15*40];   // padded rows for float4 alignment
    __shared__ float2 s_w2[8*8*64];    // [pair][icl][ky*8+kx] = (w_2p, w_2p+1)
    const int x0 = blockIdx.x * 32, y0 = blockIdx.y * 8;
    const int b = blockIdx.z;
    const int tid = threadIdx.x;
    const int pr  = tid >> 5;          // oc pair 0..7
    const int s   = tid & 31;
    const int row = s >> 2;
    const int cs  = (s & 3) * 8;

    ull acc2[8];
#pragma unroll
    for (int j = 0; j < 8; j++) acc2[j] = 0ull;

    for (int chunk = 0; chunk < CIN/8; chunk++) {
        const int ic0 = chunk * 8;
        __syncthreads();
        for (int i = tid; i < 8*15*40; i += 256) {
            int icl = i / 600;
            int r = (i / 40) % 15, c = i % 40;
            int iy = y0 + r, ix = x0 + c;
            float v = 0.f;
            if (c < 39 && iy < HIN && ix < WIN)
                v = in[(((long)b*CIN + ic0 + icl)*HIN + iy)*WIN + ix];
            s_in[i] = v;
        }
        for (int i = tid; i < 8*512; i += 256) {
            int p = i >> 9;
            int r = i & 511;           // icl*64 + k
            float w0 = w[(2*p    )*CIN*64 + ic0*64 + r];
            float w1 = w[(2*p + 1)*CIN*64 + ic0*64 + r];
            s_w2[i] = make_float2(w0, w1);
        }
        __syncthreads();

        for (int icl = 0; icl < 8; icl++) {
#pragma unroll
            for (int ky = 0; ky < 8; ky++) {
                const float* ip = &s_in[icl*600 + (row + ky)*40 + cs];
                float4 v0 = *(const float4*)(ip);
                float4 v1 = *(const float4*)(ip + 4);
                float4 v2 = *(const float4*)(ip + 8);
                float4 v3 = *(const float4*)(ip + 12);
                ull ivb[15];
                ivb[0]=bc2(v0.x); ivb[1]=bc2(v0.y); ivb[2]=bc2(v0.z); ivb[3]=bc2(v0.w);
                ivb[4]=bc2(v1.x); ivb[5]=bc2(v1.y); ivb[6]=bc2(v1.z); ivb[7]=bc2(v1.w);
                ivb[8]=bc2(v2.x); ivb[9]=bc2(v2.y); ivb[10]=bc2(v2.z); ivb[11]=bc2(v2.w);
                ivb[12]=bc2(v3.x); ivb[13]=bc2(v3.y); ivb[14]=bc2(v3.z);
                const float2* wrow = &s_w2[(pr*8 + icl)*64 + ky*8];
#pragma unroll
                for (int kx = 0; kx < 8; kx++) {
                    ull w2 = *(const ull*)&wrow[kx];
#pragma unroll
                    for (int j = 0; j < 8; j++)
                        ffma2(acc2[j], ivb[kx + j], w2);
                }
            }
        }
    }

    const int oy = y0 + row;
    if (oy < HOUT) {
        const int oc0 = 2*pr;
        const float b0 = bias[oc0], b1 = bias[oc0 + 1];
        float* o0 = &out[(((long)b*16 + oc0)*HOUT + oy)*WOUT];
        float* o1 = o0 + (long)HOUT*WOUT;
#pragma unroll
        for (int j = 0; j < 8; j++) {
            int ox = x0 + cs + j;
            if (ox < WOUT) {
                float2 f = up2(acc2[j]);
                o0[ox] = fmaxf(f.x + b0, 0.f);
                o1[ox] = fmaxf(f.y + b1, 0.f);
            }
        }
    }
}

// ===========================================================================
// conv4: 6x6 stride 2, (64,16,52,52) -> (64,16,24,24), +ReLU
// ===========================================================================
__global__ void conv4_kernel(const float* __restrict__ in,
                             const float* __restrict__ w,
                             const float* __restrict__ bias,
                             float* __restrict__ out) {
    __shared__ float s_in[8*16*52];
    __shared__ float s_w[16*8*36];
    const int band = blockIdx.x;
    const int b = blockIdx.y;
    const int tid = threadIdx.x;
    const int ry0 = band * 6;

    float acc[9];
#pragma unroll
    for (int t = 0; t < 9; t++) acc[t] = 0.f;

    for (int chunk = 0; chunk < 2; chunk++) {
        const int ic0 = chunk * 8;
        __syncthreads();
        for (int i = tid; i < 8*16*52; i += 256) {
            int icl = i / (16*52);
            int r = (i / 52) % 16, c = i % 52;
            s_in[i] = in[(((long)b*16 + ic0 + icl)*52 + 12*band + r)*52 + c];
        }
        for (int i = tid; i < 16*8*36; i += 256) {
            int o = i / (8*36);
            int r = i % (8*36);
            int icl = r / 36, k = r % 36;
            s_w[i] = w[(o*16 + ic0 + icl)*36 + k];
        }
        __syncthreads();
#pragma unroll
        for (int t = 0; t < 9; t++) {
            int task = tid + t*256;
            if (task < 2304) {
                int oc = task / 144;
                int r = task % 144;
                int row = r / 24, cx = r % 24;
                float a = acc[t];
                for (int icl = 0; icl < 8; icl++) {
#pragma unroll
                    for (int ky = 0; ky < 6; ky++) {
                        const float* rp = &s_in[(icl*16 + 2*row + ky)*52 + 2*cx];
                        const float* wpp = &s_w[(oc*8 + icl)*36 + ky*6];
#pragma unroll
                        for (int kx = 0; kx < 6; kx++) a += rp[kx] * wpp[kx];
                    }
                }
                acc[t] = a;
            }
        }
    }
#pragma unroll
    for (int t = 0; t < 9; t++) {
        int task = tid + t*256;
        if (task < 2304) {
            int oc = task / 144;
            int r = task % 144;
            int row = r / 24, cx = r % 24;
            out[(((long)b*16 + oc)*24 + ry0 + row)*24 + cx] = fmaxf(acc[t] + bias[oc], 0.f);
        }
    }
}

// ===========================================================================
// conv5: 5x5, (64,16,24,24) -> (64,16,20,20), +ReLU.
// ===========================================================================
__global__ void conv5_kernel(const float* __restrict__ in,
                             const float* __restrict__ w,
                             const float* __restrict__ bias,
                             float* __restrict__ out) {
    __shared__ float s_in[16*14*24];
    __shared__ float s_w[16*16*25];
    const int band = blockIdx.x;
    const int b = blockIdx.y;
    const int tid = threadIdx.x;
    const int ry0 = band * 10;

    for (int i = tid; i < 16*14*24; i += 256) {
        int icl = i / (14*24);
        int r = (i / 24) % 14, c = i % 24;
        s_in[i] = in[(((long)b*16 + icl)*24 + ry0 + r)*24 + c];
    }
    for (int i = tid; i < 16*16*25; i += 256)
        s_w[i] = w[i];
    __syncthreads();

#pragma unroll
    for (int t = 0; t < 13; t++) {
        int task = tid + t*256;
        if (task < 3200) {
            int oc = task / 200;
            int r = task % 200;
            int row = r / 20, cx = r % 20;
            float a = 0.f;
            for (int ic = 0; ic < 16; ic++) {
#pragma unroll
                for (int ky = 0; ky < 5; ky++) {
                    const float* rp = &s_in[(ic*14 + row + ky)*24 + cx];
                    const float* wpp = &s_w[(oc*16 + ic)*25 + ky*5];
#pragma unroll
                    for (int kx = 0; kx < 5; kx++) a += rp[kx] * wpp[kx];
                }
            }
            out[(((long)b*16 + oc)*20 + ry0 + row)*20 + cx] = fmaxf(a + bias[oc], 0.f);
        }
    }
}

// ===========================================================================
// GEMM for fc1/fc2:  out(64,N) = relu(X(64,K) @ W(N,K)^T + b)
// ===========================================================================
__global__ void __launch_bounds__(256)
gemm_relu_kernel(const float* __restrict__ X,
                 const float* __restrict__ W,
                 const float* __restrict__ bias,
                 float* __restrict__ out,
                 int N, int K) {
    __shared__ float xs[64][68];
    __shared__ float ws[64][68];
    const int n0 = blockIdx.x * 64;
    const int tid = threadIdx.x;
    const int tx = tid & 15, ty = tid >> 4;

    float acc[4][4];
#pragma unroll
    for (int i = 0; i < 4; i++)
#pragma unroll
        for (int j = 0; j < 4; j++) acc[i][j] = 0.f;

    for (int k0 = 0; k0 < K; k0 += 64) {
        __syncthreads();
        for (int i = tid; i < 64*64; i += 256) {
            int m = i >> 6, k = i & 63;
            xs[k][m] = X[m*K + k0 + k];
        }
        for (int i = tid; i < 64*64; i += 256) {
            int n = i >> 6, k = i & 63;
            ws[k][n] = W[(long)(n0 + n)*K + k0 + k];
        }
        __syncthreads();
#pragma unroll 8
        for (int k = 0; k < 64; k++) {
            float4 a4 = *(const float4*)&xs[k][ty*4];
            float4 b4 = *(const float4*)&ws[k][tx*4];
            float a[4] = {a4.x, a4.y, a4.z, a4.w};
            float bb[4] = {b4.x, b4.y, b4.z, b4.w};
#pragma unroll
            for (int i = 0; i < 4; i++)
#pragma unroll
                for (int j = 0; j < 4; j++)
                    acc[i][j] += a[i] * bb[j];
        }
    }
#pragma unroll
    for (int i = 0; i < 4; i++) {
        int m = ty*4 + i;
#pragma unroll
        for (int j = 0; j < 4; j++) {
            int n = n0 + tx*4 + j;
            out[m*N + n] = fmaxf(acc[i][j] + bias[n], 0.f);
        }
    }
}

// ===========================================================================
// fc3: (64,2048) @ (12,2048)^T + b -> (64,12).  One warp per output.
// ===========================================================================
__global__ void fc3_kernel(const float* __restrict__ X,
                           const float* __restrict__ W,
                           const float* __restrict__ bias,
                           float* __restrict__ out) {
    const int warp = (blockIdx.x * 256 + threadIdx.x) >> 5;
    const int lane = threadIdx.x & 31;
    if (warp >= 768) return;
    const int m = warp / 12, n = warp % 12;
    float s = 0.f;
    for (int k = lane; k < 2048; k += 32)
        s += X[m*2048 + k] * W[n*2048 + k];
#pragma unroll
    for (int o = 16; o; o >>= 1) s += __shfl_xor_sync(0xFFFFFFFFu, s, o);
    if (lane == 0) out[m*12 + n] = s + bias[n];
}

// ===========================================================================
extern "C" void kernel_launch(void* const* d_in, const int* in_sizes, int n_in,
                              void* d_out, int out_size) {
    const float* x       = (const float*)d_in[0];
    const float* conv1_w = (const float*)d_in[1];
    const float* conv1_b = (const float*)d_in[2];
    const float* rg_g    = (const float*)d_in[3];
    const float* rg_b    = (const float*)d_in[4];
    const float* rg_m    = (const float*)d_in[5];
    const float* rg_v    = (const float*)d_in[6];
    const float* rg_w    = (const float*)d_in[7];
    const float* rg_cb   = (const float*)d_in[8];
    const float* bn2_g   = (const float*)d_in[9];
    const float* bn2_b   = (const float*)d_in[10];
    const float* bn2_m   = (const float*)d_in[11];
    const float* bn2_v   = (const float*)d_in[12];
    const float* conv2_w = (const float*)d_in[13];
    const float* conv2_b = (const float*)d_in[14];
    const float* conv3_w = (const float*)d_in[15];
    const float* conv3_b = (const float*)d_in[16];
    const float* conv4_w = (const float*)d_in[17];
    const float* conv4_b = (const float*)d_in[18];
    const float* conv5_w = (const float*)d_in[19];
    const float* conv5_b = (const float*)d_in[20];
    const float* fc1_w   = (const float*)d_in[21];
    const float* fc1_b   = (const float*)d_in[22];
    const float* fc2_w   = (const float*)d_in[23];
    const float* fc2_b   = (const float*)d_in[24];
    const float* fc3_w   = (const float*)d_in[25];
    const float* fc3_b   = (const float*)d_in[26];

    float *b1, *b2, *b3, *b4, *b5, *b6, *f1, *f2;
    cudaGetSymbolAddress((void**)&b1, g_buf1);
    cudaGetSymbolAddress((void**)&b2, g_buf2);
    cudaGetSymbolAddress((void**)&b3, g_buf3);
    cudaGetSymbolAddress((void**)&b4, g_buf4);
    cudaGetSymbolAddress((void**)&b5, g_buf5);
    cudaGetSymbolAddress((void**)&b6, g_buf6);
    cudaGetSymbolAddress((void**)&f1, g_fc1o);
    cudaGetSymbolAddress((void**)&f2, g_fc2o);

    conv1_kernel<<<dim3(12, 8, 64), 264>>>(x, conv1_w, conv1_b, b1);
    region_kernel<<<dim3(64, 64), 288>>>(b1, rg_g, rg_b, rg_m, rg_v, rg_w, rg_cb,
                                         bn2_g, bn2_b, bn2_m, bn2_v, b2);
    conv8x8_relu_kernel<32, 66, 66, 59, 59><<<dim3(2, 8, 64), 256>>>(b2, conv2_w, conv2_b, b3);
    conv8x8_relu_kernel<16, 59, 59, 52, 52><<<dim3(2, 7, 64), 256>>>(b3, conv3_w, conv3_b, b4);
    conv4_kernel<<<dim3(4, 64), 256>>>(b4, conv4_w, conv4_b, b5);
    conv5_kernel<<<dim3(2, 64), 256>>>(b5, conv5_w, conv5_b, b6);
    gemm_relu_kernel<<<64, 256>>>(b6, fc1_w, fc1_b, f1, 4096, 6400);
    gemm_relu_kernel<<<32, 256>>>(f1, fc2_w, fc2_b, f2, 2048, 4096);
    fc3_kernel<<<96, 256>>>(f2, fc3_w, fc3_b, (float*)d_out);
}